// round 1
// baseline (speedup 1.0000x reference)
#include <cuda_runtime.h>
#include <math.h>

#define NB 2
#define NS 2048
#define ND 1024
#define NH 16
#define DH 64
#define NM (NB*NS)   // 4096 rows

// Scratch (allocation-free rule -> __device__ globals). 4x16MB = 64MB.
__device__ float g_q[NB*NH*NS*DH];
__device__ float g_k[NB*NH*NS*DH];
__device__ float g_v[NB*NH*NS*DH];
__device__ float g_ao[NM*ND];

// ---------------------------------------------------------------------------
// Fused QKV projection GEMM: C = X[4096,1024] * W[1024,1024] + bias
// blockIdx.z selects (wq,bq)->g_q, (wk,bk)->g_k, (wv,bv)->g_v.
// Output stored head-split: [b][h][s][d].
// Tiling: 128x128x8, 256 threads, 8x8 microtile per thread.
// ---------------------------------------------------------------------------
__global__ __launch_bounds__(256) void qkv_gemm_kernel(
    const float* __restrict__ X,
    const float* __restrict__ wq, const float* __restrict__ wk, const float* __restrict__ wv,
    const float* __restrict__ bq, const float* __restrict__ bk, const float* __restrict__ bv)
{
    const float* W; const float* bias; float* out;
    if (blockIdx.z == 0)      { W = wq; bias = bq; out = g_q; }
    else if (blockIdx.z == 1) { W = wk; bias = bk; out = g_k; }
    else                      { W = wv; bias = bv; out = g_v; }

    __shared__ float As[8][128];
    __shared__ float Bs[8][128];

    const int tid  = threadIdx.x;
    const int brow = blockIdx.y * 128;
    const int bcol = blockIdx.x * 128;

    float acc[8][8];
    #pragma unroll
    for (int i = 0; i < 8; i++)
        #pragma unroll
        for (int j = 0; j < 8; j++) acc[i][j] = 0.f;

    const int aRow = tid >> 1, aCol = (tid & 1) * 4;
    const int bRow = tid >> 5, bCol = (tid & 31) * 4;
    const float* Ap = X + (brow + aRow) * ND + aCol;
    const float* Bp = W + bRow * ND + bcol + bCol;

    const int tr = tid >> 4, tc = tid & 15;

    for (int k0 = 0; k0 < ND; k0 += 8) {
        float4 a4 = *(const float4*)(Ap + k0);
        float4 b4 = *(const float4*)(Bp + k0 * ND);
        As[aCol + 0][aRow] = a4.x;
        As[aCol + 1][aRow] = a4.y;
        As[aCol + 2][aRow] = a4.z;
        As[aCol + 3][aRow] = a4.w;
        *(float4*)&Bs[bRow][bCol] = b4;
        __syncthreads();

        #pragma unroll
        for (int kk = 0; kk < 8; kk++) {
            float ra[8], rb[8];
            *(float4*)&ra[0] = *(const float4*)&As[kk][tr * 8];
            *(float4*)&ra[4] = *(const float4*)&As[kk][tr * 8 + 4];
            *(float4*)&rb[0] = *(const float4*)&Bs[kk][tc * 8];
            *(float4*)&rb[4] = *(const float4*)&Bs[kk][tc * 8 + 4];
            #pragma unroll
            for (int i = 0; i < 8; i++)
                #pragma unroll
                for (int j = 0; j < 8; j++)
                    acc[i][j] += ra[i] * rb[j];
        }
        __syncthreads();
    }

    #pragma unroll
    for (int i = 0; i < 8; i++) {
        int row = brow + tr * 8 + i;
        int b = row >> 11;            // /2048
        int s = row & (NS - 1);
        #pragma unroll
        for (int j = 0; j < 8; j++) {
            int col = bcol + tc * 8 + j;
            int h = col >> 6, d = col & 63;
            out[((b * NH + h) * NS + s) * DH + d] = acc[i][j] + bias[col];
        }
    }
}

// ---------------------------------------------------------------------------
// RoPE applied in place to g_q and g_k. One thread per (b,h,s, d in [0,32)).
// Pair (d, d+32): angles use freq idx d/2 and d/2+16 (repeat-2 cos layout).
// Angles generated in double to stay well within the 1e-3 budget.
// ---------------------------------------------------------------------------
__global__ void rope_kernel() {
    const int total = NB * NH * NS * 32;
    int idx = blockIdx.x * blockDim.x + threadIdx.x;
    if (idx >= total) return;
    int d  = idx & 31;
    int s  = (idx >> 5) & (NS - 1);
    int bh = idx >> 16;               // 5 + 11 bits

    int t1 = d >> 1;
    int t2 = t1 + 16;
    double inv1 = pow(10000.0, -(double)t1 / 32.0);
    double inv2 = pow(10000.0, -(double)t2 / 32.0);
    float a1 = (float)((double)s * inv1);
    float a2 = (float)((double)s * inv2);
    float c1, s1, c2, s2;
    sincosf(a1, &s1, &c1);
    sincosf(a2, &s2, &c2);

    int base = (bh * NS + s) * DH + d;

    float x1 = g_q[base], x2 = g_q[base + 32];
    g_q[base]      = x1 * c1 - x2 * s1;
    g_q[base + 32] = x2 * c2 + x1 * s2;

    x1 = g_k[base]; x2 = g_k[base + 32];
    g_k[base]      = x1 * c1 - x2 * s1;
    g_k[base + 32] = x2 * c2 + x1 * s2;
}

// ---------------------------------------------------------------------------
// Flash attention: block = (b, h, 64-query tile), 256 threads.
// Score/PV tiles 64x64, each thread owns a 4x4 microtile (tr=rows, tc=cols).
// smem row stride 65 to break stride-64 bank conflicts.
// KP buffer holds K during scores, then reused for P during PV.
// ---------------------------------------------------------------------------
#define ATT_STRIDE 65
#define ATT_SMEM (3 * 64 * ATT_STRIDE * (int)sizeof(float))

__global__ __launch_bounds__(256) void attn_kernel(const int* __restrict__ mask) {
    extern __shared__ float sm[];
    float* Qs = sm;
    float* KP = sm + 64 * ATT_STRIDE;
    float* Vs = sm + 2 * 64 * ATT_STRIDE;
    __shared__ float maskS[64];

    const int tid = threadIdx.x;
    const int q0 = blockIdx.x * 64;
    const int h  = blockIdx.y;
    const int b  = blockIdx.z;
    const float* Qg = g_q + ((b * NH + h) * NS) * DH;
    const float* Kg = g_k + ((b * NH + h) * NS) * DH;
    const float* Vg = g_v + ((b * NH + h) * NS) * DH;

    // load Q tile (64 x 64)
    for (int i = tid; i < 64 * 16; i += 256) {
        int r = i >> 4, c = (i & 15) * 4;
        float4 v = *(const float4*)(Qg + (q0 + r) * DH + c);
        Qs[r * ATT_STRIDE + c + 0] = v.x;
        Qs[r * ATT_STRIDE + c + 1] = v.y;
        Qs[r * ATT_STRIDE + c + 2] = v.z;
        Qs[r * ATT_STRIDE + c + 3] = v.w;
    }

    const int tr = tid >> 4;   // row group: rows tr*4 .. tr*4+3 (lanes 0-15 / 16-31 split)
    const int tc = tid & 15;   // col group: cols tc*4 .. tc*4+3

    float m[4], l[4], acc[4][4];
    #pragma unroll
    for (int i = 0; i < 4; i++) {
        m[i] = -3e38f; l[i] = 0.f;
        #pragma unroll
        for (int j = 0; j < 4; j++) acc[i][j] = 0.f;
    }

    for (int kt = 0; kt < NS / 64; kt++) {
        const int k0 = kt * 64;
        __syncthreads();   // previous iteration's smem reads complete
        for (int i = tid; i < 64 * 16; i += 256) {
            int r = i >> 4, c = (i & 15) * 4;
            float4 kv = *(const float4*)(Kg + (k0 + r) * DH + c);
            KP[r * ATT_STRIDE + c + 0] = kv.x;
            KP[r * ATT_STRIDE + c + 1] = kv.y;
            KP[r * ATT_STRIDE + c + 2] = kv.z;
            KP[r * ATT_STRIDE + c + 3] = kv.w;
            float4 vv = *(const float4*)(Vg + (k0 + r) * DH + c);
            Vs[r * ATT_STRIDE + c + 0] = vv.x;
            Vs[r * ATT_STRIDE + c + 1] = vv.y;
            Vs[r * ATT_STRIDE + c + 2] = vv.z;
            Vs[r * ATT_STRIDE + c + 3] = vv.w;
        }
        if (tid < 64) maskS[tid] = -1e9f * (float)mask[b * NS + k0 + tid];
        __syncthreads();

        // ---- scores: 4x4 microtile of Q @ K^T ----
        float sc[4][4];
        #pragma unroll
        for (int i = 0; i < 4; i++)
            #pragma unroll
            for (int j = 0; j < 4; j++) sc[i][j] = 0.f;

        #pragma unroll 8
        for (int d = 0; d < 64; d++) {
            float qv[4], kv[4];
            #pragma unroll
            for (int i = 0; i < 4; i++) qv[i] = Qs[(tr * 4 + i) * ATT_STRIDE + d];
            #pragma unroll
            for (int j = 0; j < 4; j++) kv[j] = KP[(tc * 4 + j) * ATT_STRIDE + d];
            #pragma unroll
            for (int i = 0; i < 4; i++)
                #pragma unroll
                for (int j = 0; j < 4; j++)
                    sc[i][j] += qv[i] * kv[j];
        }

        // ---- online softmax (row reduce across the 16 lanes of a row group) ----
        #pragma unroll
        for (int i = 0; i < 4; i++) {
            float mx = -3e38f;
            #pragma unroll
            for (int j = 0; j < 4; j++) {
                sc[i][j] = sc[i][j] * 0.125f + maskS[tc * 4 + j];
                mx = fmaxf(mx, sc[i][j]);
            }
            mx = fmaxf(mx, __shfl_xor_sync(0xffffffffu, mx, 1));
            mx = fmaxf(mx, __shfl_xor_sync(0xffffffffu, mx, 2));
            mx = fmaxf(mx, __shfl_xor_sync(0xffffffffu, mx, 4));
            mx = fmaxf(mx, __shfl_xor_sync(0xffffffffu, mx, 8));
            float mnew  = fmaxf(m[i], mx);
            float alpha = __expf(m[i] - mnew);
            float ls = 0.f;
            #pragma unroll
            for (int j = 0; j < 4; j++) {
                sc[i][j] = __expf(sc[i][j] - mnew);
                ls += sc[i][j];
            }
            ls += __shfl_xor_sync(0xffffffffu, ls, 1);
            ls += __shfl_xor_sync(0xffffffffu, ls, 2);
            ls += __shfl_xor_sync(0xffffffffu, ls, 4);
            ls += __shfl_xor_sync(0xffffffffu, ls, 8);
            l[i] = l[i] * alpha + ls;
            m[i] = mnew;
            #pragma unroll
            for (int j = 0; j < 4; j++) acc[i][j] *= alpha;
        }

        __syncthreads();   // everyone done reading KP as K
        #pragma unroll
        for (int i = 0; i < 4; i++)
            #pragma unroll
            for (int j = 0; j < 4; j++)
                KP[(tr * 4 + i) * ATT_STRIDE + tc * 4 + j] = sc[i][j];
        __syncthreads();

        // ---- PV accumulate: 4x4 microtile of P @ V ----
        #pragma unroll 8
        for (int k = 0; k < 64; k++) {
            float p[4], vv[4];
            #pragma unroll
            for (int i = 0; i < 4; i++) p[i] = KP[(tr * 4 + i) * ATT_STRIDE + k];
            #pragma unroll
            for (int j = 0; j < 4; j++) vv[j] = Vs[k * ATT_STRIDE + tc * 4 + j];
            #pragma unroll
            for (int i = 0; i < 4; i++)
                #pragma unroll
                for (int j = 0; j < 4; j++)
                    acc[i][j] += p[i] * vv[j];
        }
    }

    // writeback to [b][s][h*DH+d] layout for the output projection
    #pragma unroll
    for (int i = 0; i < 4; i++) {
        float inv = 1.f / l[i];
        int s = q0 + tr * 4 + i;
        float* dst = g_ao + (b * NS + s) * ND + h * DH + tc * 4;
        #pragma unroll
        for (int j = 0; j < 4; j++) dst[j] = acc[i][j] * inv;
    }
}

// ---------------------------------------------------------------------------
// Output projection: d_out = g_ao[4096,1024] * wo + bo  (plain row-major out)
// ---------------------------------------------------------------------------
__global__ __launch_bounds__(256) void out_gemm_kernel(
    const float* __restrict__ wo, const float* __restrict__ bo,
    float* __restrict__ C)
{
    __shared__ float As[8][128];
    __shared__ float Bs[8][128];

    const int tid  = threadIdx.x;
    const int brow = blockIdx.y * 128;
    const int bcol = blockIdx.x * 128;

    float acc[8][8];
    #pragma unroll
    for (int i = 0; i < 8; i++)
        #pragma unroll
        for (int j = 0; j < 8; j++) acc[i][j] = 0.f;

    const int aRow = tid >> 1, aCol = (tid & 1) * 4;
    const int bRow = tid >> 5, bCol = (tid & 31) * 4;
    const float* Ap = g_ao + (brow + aRow) * ND + aCol;
    const float* Bp = wo + bRow * ND + bcol + bCol;

    const int tr = tid >> 4, tc = tid & 15;

    for (int k0 = 0; k0 < ND; k0 += 8) {
        float4 a4 = *(const float4*)(Ap + k0);
        float4 b4 = *(const float4*)(Bp + k0 * ND);
        As[aCol + 0][aRow] = a4.x;
        As[aCol + 1][aRow] = a4.y;
        As[aCol + 2][aRow] = a4.z;
        As[aCol + 3][aRow] = a4.w;
        *(float4*)&Bs[bRow][bCol] = b4;
        __syncthreads();

        #pragma unroll
        for (int kk = 0; kk < 8; kk++) {
            float ra[8], rb[8];
            *(float4*)&ra[0] = *(const float4*)&As[kk][tr * 8];
            *(float4*)&ra[4] = *(const float4*)&As[kk][tr * 8 + 4];
            *(float4*)&rb[0] = *(const float4*)&Bs[kk][tc * 8];
            *(float4*)&rb[4] = *(const float4*)&Bs[kk][tc * 8 + 4];
            #pragma unroll
            for (int i = 0; i < 8; i++)
                #pragma unroll
                for (int j = 0; j < 8; j++)
                    acc[i][j] += ra[i] * rb[j];
        }
        __syncthreads();
    }

    #pragma unroll
    for (int i = 0; i < 8; i++) {
        int row = brow + tr * 8 + i;
        #pragma unroll
        for (int j = 0; j < 8; j++) {
            int col = bcol + tc * 8 + j;
            C[row * ND + col] = acc[i][j] + bo[col];
        }
    }
}

// ---------------------------------------------------------------------------
extern "C" void kernel_launch(void* const* d_in, const int* in_sizes, int n_in,
                              void* d_out, int out_size) {
    const float* x    = (const float*)d_in[0];
    const int*   mask = (const int*)  d_in[1];
    const float* wq   = (const float*)d_in[2];
    const float* bq   = (const float*)d_in[3];
    const float* wk   = (const float*)d_in[4];
    const float* bk   = (const float*)d_in[5];
    const float* wv   = (const float*)d_in[6];
    const float* bv   = (const float*)d_in[7];
    const float* wo   = (const float*)d_in[8];
    const float* bo   = (const float*)d_in[9];
    float* out = (float*)d_out;

    // allow >48KB dynamic smem for the attention kernel (idempotent host call)
    cudaFuncSetAttribute(attn_kernel, cudaFuncAttributeMaxDynamicSharedMemorySize, ATT_SMEM);

    dim3 gGemm(ND / 128, NM / 128, 3);
    qkv_gemm_kernel<<<gGemm, 256>>>(x, wq, wk, wv, bq, bk, bv);

    const int ropeTotal = NB * NH * NS * 32;
    rope_kernel<<<(ropeTotal + 255) / 256, 256>>>();

    dim3 gAttn(NS / 64, NH, NB);
    attn_kernel<<<gAttn, 256, ATT_SMEM>>>(mask);

    dim3 gOut(ND / 128, NM / 128, 1);
    out_gemm_kernel<<<gOut, 256>>>(wo, bo, out);
}

// round 13
// speedup vs baseline: 2.4213x; 2.4213x over previous
#include <cuda_runtime.h>
#include <cuda_bf16.h>
#include <cstdint>
#include <math.h>

#define NB 2
#define NS 2048
#define ND 1024
#define NH 16
#define DH 64
#define NM (NB*NS)     // 4096
#define BHT (NB*NH)    // 32

// ---------------- scratch (__device__ globals; allocation-free rule) -------
__device__ __nv_bfloat16 g_xhi[NM*ND],  g_xlo[NM*ND];
__device__ __nv_bfloat16 g_wthi[4*ND*ND], g_wtlo[4*ND*ND];     // W^T per weight
__device__ __nv_bfloat16 g_qhi[BHT*NS*DH], g_qlo[BHT*NS*DH];
__device__ __nv_bfloat16 g_khi[BHT*NS*DH], g_klo[BHT*NS*DH];
__device__ __nv_bfloat16 g_vthi[BHT*DH*NS], g_vtlo[BHT*DH*NS]; // V^T per (b,h)
__device__ float        g_logits[(size_t)BHT*NS*NS];           // 512MB
__device__ __nv_bfloat16 g_phi[(size_t)BHT*NS*NS], g_plo[(size_t)BHT*NS*NS];
__device__ __nv_bfloat16 g_aohi[NM*ND], g_aolo[NM*ND];
__device__ float g_rc[NS*32], g_rs[NS*32];                     // RoPE cos/sin table

// ---------------- warp MMA helpers (sm_80+ mma.sync, works on sm_103) ------
__device__ __forceinline__ uint32_t smem_u32(const void* p) {
    uint32_t a;
    asm("{ .reg .u64 t; cvta.to.shared.u64 t, %1; cvt.u32.u64 %0, t; }" : "=r"(a) : "l"(p));
    return a;
}
#define LDSM4(r, a) \
    asm volatile("ldmatrix.sync.aligned.m8n8.x4.shared.b16 {%0,%1,%2,%3}, [%4];" \
        : "=r"((r)[0]), "=r"((r)[1]), "=r"((r)[2]), "=r"((r)[3]) : "r"(a))

__device__ __forceinline__ void mma16816(float* c, const uint32_t* a, const uint32_t* b) {
    asm volatile(
        "mma.sync.aligned.m16n8k16.row.col.f32.bf16.bf16.f32 "
        "{%0,%1,%2,%3}, {%4,%5,%6,%7}, {%8,%9}, {%0,%1,%2,%3};"
        : "+f"(c[0]), "+f"(c[1]), "+f"(c[2]), "+f"(c[3])
        : "r"(a[0]), "r"(a[1]), "r"(a[2]), "r"(a[3]), "r"(b[0]), "r"(b[1]));
}

// ---------------- hi/lo bf16 pair GEMM core (HMMA) --------------------------
// C[128,NT] += (Ahi+Alo)(Bhi+Blo)^T over ktot (drops lo*lo).
// A: 128 rows stride lda; B: NT rows stride ldb (both K-major bf16).
// 256 threads = 8 warps, warp tile WM x WN (grid (128/WM) x (NT/WN) = 8).
// acc layout: [mt][nt][4], mt<WM/16, nt<WN/8.
#define STRH 72                 // smem row stride in halves (144B, conflict-free)
#define STRB 144
template<int NT, int WM, int WN>
__device__ __forceinline__ void hmma_core(
    const __nv_bfloat16* __restrict__ Ahi, const __nv_bfloat16* __restrict__ Alo, int lda,
    const __nv_bfloat16* __restrict__ Bhi, const __nv_bfloat16* __restrict__ Blo, int ldb,
    int ktot, char* dsm, float* acc)
{
    constexpr int KC   = 64;
    constexpr int A_SZ = 128*STRB;
    constexpr int B_SZ = NT*STRB;
    constexpr int OFF_ALO = A_SZ, OFF_BHI = 2*A_SZ, OFF_BLO = 2*A_SZ + B_SZ;
    constexpr int WARPS_N = NT/WN;
    constexpr int MT = WM/16, NTT = WN/8;

    const int tid = threadIdx.x, lane = tid & 31, w = tid >> 5;
    const int wm = w / WARPS_N, wn = w % WARPS_N;
    const uint32_t sb = smem_u32(dsm);

    #pragma unroll
    for (int i = 0; i < MT*NTT*4; i++) acc[i] = 0.f;

    // per-thread ldmatrix smem offsets (within a k-chunk)
    const uint32_t aro = (uint32_t)(wm*WM + (lane & 15)) * STRB + (lane >> 4) * 16;
    const uint32_t bro = (uint32_t)(wn*WN + (lane & 7) + (lane >> 4) * 8) * STRB
                       + ((lane >> 3) & 1) * 16;

    for (int k0 = 0; k0 < ktot; k0 += KC) {
        for (int i = tid; i < 128*8; i += 256) {
            int r = i >> 3, u = i & 7;
            int so = r*STRB + u*16;
            const size_t off = (size_t)r*lda + k0 + u*8;
            *(uint4*)(dsm + so)           = *(const uint4*)(Ahi + off);
            *(uint4*)(dsm + OFF_ALO + so) = *(const uint4*)(Alo + off);
        }
        for (int i = tid; i < NT*8; i += 256) {
            int r = i >> 3, u = i & 7;
            int so = r*STRB + u*16;
            const size_t off = (size_t)r*ldb + k0 + u*8;
            *(uint4*)(dsm + OFF_BHI + so) = *(const uint4*)(Bhi + off);
            *(uint4*)(dsm + OFF_BLO + so) = *(const uint4*)(Blo + off);
        }
        __syncthreads();

        #pragma unroll
        for (int ks = 0; ks < KC/16; ks++) {
            uint32_t ah[MT][4], al[MT][4];
            #pragma unroll
            for (int mt = 0; mt < MT; mt++) {
                uint32_t ro = aro + (uint32_t)mt*16*STRB + ks*32;
                LDSM4(ah[mt], sb + ro);
                LDSM4(al[mt], sb + OFF_ALO + ro);
            }
            uint32_t bh[NTT][2], bl[NTT][2];
            #pragma unroll
            for (int np = 0; np < NTT/2; np++) {
                uint32_t ro = bro + (uint32_t)np*16*STRB + ks*32;
                uint32_t t4[4];
                LDSM4(t4, sb + OFF_BHI + ro);
                bh[2*np][0] = t4[0]; bh[2*np][1] = t4[1];
                bh[2*np+1][0] = t4[2]; bh[2*np+1][1] = t4[3];
                LDSM4(t4, sb + OFF_BLO + ro);
                bl[2*np][0] = t4[0]; bl[2*np][1] = t4[1];
                bl[2*np+1][0] = t4[2]; bl[2*np+1][1] = t4[3];
            }
            #pragma unroll
            for (int mt = 0; mt < MT; mt++)
                #pragma unroll
                for (int nt = 0; nt < NTT; nt++) {
                    float* c = acc + (mt*NTT + nt)*4;
                    mma16816(c, ah[mt], bh[nt]);   // hi*hi
                    mma16816(c, ah[mt], bl[nt]);   // hi*lo
                    mma16816(c, al[mt], bh[nt]);   // lo*hi
                }
        }
        __syncthreads();
    }
}

// ---------------- RoPE cos/sin table ---------------------------------------
__global__ void k_rope_tab() {
    int i = blockIdx.x * 256 + threadIdx.x;   // i = s*32 + t
    int t = i & 31, s = i >> 5;
    double inv = pow(10000.0, -(double)t / 32.0);
    float a = (float)((double)s * inv);
    g_rc[i] = cosf(a);
    g_rs[i] = sinf(a);
}

// ---------------- conversions ----------------------------------------------
__global__ void k_convert_x(const float* __restrict__ x) {
    int i = blockIdx.x * 256 + threadIdx.x;
    float v = x[i];
    __nv_bfloat16 h = __float2bfloat16(v);
    g_xhi[i] = h;
    g_xlo[i] = __float2bfloat16(v - __bfloat162float(h));
}

__global__ void k_wtrans(const float* __restrict__ wq, const float* __restrict__ wk,
                         const float* __restrict__ wv, const float* __restrict__ wo) {
    __shared__ float t[32][33];
    const int z = blockIdx.z;
    const float* w = (z == 0) ? wq : (z == 1) ? wk : (z == 2) ? wv : wo;
    __nv_bfloat16* oh = g_wthi + (size_t)z*ND*ND;
    __nv_bfloat16* ol = g_wtlo + (size_t)z*ND*ND;
    int bx = blockIdx.x * 32, by = blockIdx.y * 32;
    int tx = threadIdx.x, ty = threadIdx.y;           // block (32, 8)
    #pragma unroll
    for (int j = 0; j < 4; j++)
        t[ty + j*8][tx] = w[(size_t)(by + ty + j*8)*ND + bx + tx];
    __syncthreads();
    #pragma unroll
    for (int j = 0; j < 4; j++) {
        float v = t[tx][ty + j*8];                    // = w[by+tx][bx+ty+j*8]
        int n = bx + ty + j*8, kk = by + tx;
        __nv_bfloat16 h = __float2bfloat16(v);
        oh[(size_t)n*ND + kk] = h;
        ol[(size_t)n*ND + kk] = __float2bfloat16(v - __bfloat162float(h));
    }
}

// ---------------- QKV projection + fused bias/RoPE/split/V^T ---------------
__global__ __launch_bounds__(256) void k_qkv_mma(
    const float* __restrict__ bq, const float* __restrict__ bk, const float* __restrict__ bv)
{
    extern __shared__ char dsm[];
    const int z = blockIdx.z;
    const __nv_bfloat16* wh = g_wthi + (size_t)z*ND*ND;
    const __nv_bfloat16* wl = g_wtlo + (size_t)z*ND*ND;
    const float* bias = (z == 0) ? bq : (z == 1) ? bk : bv;

    const int brow = blockIdx.y * 128, bcol = blockIdx.x * 128;
    float acc[64];
    hmma_core<128, 64, 32>(g_xhi + (size_t)brow*ND, g_xlo + (size_t)brow*ND, ND,
                           wh + (size_t)bcol*ND,   wl + (size_t)bcol*ND,   ND,
                           ND, dsm, acc);
    const int tid = threadIdx.x, lane = tid & 31, w = tid >> 5;
    const int wm = w >> 2, wn = w & 3;
    float* smf = (float*)dsm;   // 128x128 fp32 tile, stride 129 (hmma done with smem)
    #pragma unroll
    for (int mt = 0; mt < 4; mt++)
        #pragma unroll
        for (int nt = 0; nt < 4; nt++)
            #pragma unroll
            for (int i = 0; i < 4; i++) {
                int row = wm*64 + mt*16 + (lane >> 2) + (i >> 1)*8;
                int col = wn*32 + nt*8 + (lane & 3)*2 + (i & 1);
                smf[row*129 + col] = acc[(mt*4 + nt)*4 + i] + bias[bcol + col];
            }
    __syncthreads();

    const int b  = brow >> 11;
    const int s0 = brow & (NS - 1);
    if (z < 2) {
        __nv_bfloat16* oh = (z == 0) ? g_qhi : g_khi;
        __nv_bfloat16* ol = (z == 0) ? g_qlo : g_klo;
        for (int i = tid; i < 128*64; i += 256) {      // pairs (d, d+32) per head
            int d  = i & 31;
            int hl = (i >> 5) & 1;
            int r  = i >> 6;
            int h  = (bcol >> 6) + hl;
            int s  = s0 + r;
            float x1 = smf[r*129 + hl*64 + d];
            float x2 = smf[r*129 + hl*64 + d + 32];
            int t1 = d >> 1;
            float c1 = g_rc[s*32 + t1],      s1 = g_rs[s*32 + t1];
            float c2 = g_rc[s*32 + t1 + 16], s2 = g_rs[s*32 + t1 + 16];
            float y1 = x1 * c1 - x2 * s1;
            float y2 = x2 * c2 + x1 * s2;
            size_t base = (((size_t)b*NH + h)*NS + s)*DH;
            __nv_bfloat16 h1 = __float2bfloat16(y1);
            oh[base + d]      = h1;
            ol[base + d]      = __float2bfloat16(y1 - __bfloat162float(h1));
            __nv_bfloat16 h2 = __float2bfloat16(y2);
            oh[base + d + 32] = h2;
            ol[base + d + 32] = __float2bfloat16(y2 - __bfloat162float(h2));
        }
    } else {
        for (int i = tid; i < 128*128; i += 256) {     // transpose: lanes sweep s
            int r = i & 127, c = i >> 7;
            int h = (bcol >> 6) + (c >> 6), d = c & 63;
            int s = s0 + r;
            float v = smf[r*129 + c];
            size_t o = (((size_t)b*NH + h)*DH + d)*NS + s;
            __nv_bfloat16 hh = __float2bfloat16(v);
            g_vthi[o] = hh;
            g_vtlo[o] = __float2bfloat16(v - __bfloat162float(hh));
        }
    }
}

// ---------------- QK^T: per (b,h) 2048x2048x64 -> raw logits fp32 ----------
__global__ __launch_bounds__(256) void k_qkt_mma() {
    extern __shared__ char dsm[];
    const int bh = blockIdx.z, q0 = blockIdx.y * 128, n0 = blockIdx.x * 128;
    const size_t offA = ((size_t)bh*NS + q0) * DH;
    const size_t offB = ((size_t)bh*NS + n0) * DH;
    float acc[64];
    hmma_core<128, 64, 32>(g_qhi + offA, g_qlo + offA, DH,
                           g_khi + offB, g_klo + offB, DH, DH, dsm, acc);
    const int lane = threadIdx.x & 31, w = threadIdx.x >> 5;
    const int wm = w >> 2, wn = w & 3;
    #pragma unroll
    for (int mt = 0; mt < 4; mt++)
        #pragma unroll
        for (int nt = 0; nt < 4; nt++) {
            int row = wm*64 + mt*16 + (lane >> 2);
            int col = n0 + wn*32 + nt*8 + (lane & 3)*2;
            float* c = acc + (mt*4 + nt)*4;
            float* lg0 = g_logits + ((size_t)bh*NS + q0 + row)*NS + col;
            *(float2*)lg0            = make_float2(c[0], c[1]);
            *(float2*)(lg0 + 8*(size_t)NS) = make_float2(c[2], c[3]);
        }
}

// ---------------- softmax rows -> bf16 hi/lo P ------------------------------
__global__ __launch_bounds__(256) void k_softmax(const int* __restrict__ mask) {
    const int row = blockIdx.x;           // = bh*NS + q
    const int b = row >> 15;
    const float* lrow = g_logits + (size_t)row * NS;
    __shared__ float red[8];
    const int tid = threadIdx.x;

    float v[8];
    float mx = -3e38f;
    #pragma unroll
    for (int t = 0; t < 8; t++) {
        int i = tid + t*256;
        float m = (float)mask[b*NS + i];
        v[t] = lrow[i] * 0.125f - 1e9f * m;
        mx = fmaxf(mx, v[t]);
    }
    #pragma unroll
    for (int o = 16; o; o >>= 1) mx = fmaxf(mx, __shfl_xor_sync(0xffffffffu, mx, o));
    if ((tid & 31) == 0) red[tid >> 5] = mx;
    __syncthreads();
    float m8 = red[0];
    #pragma unroll
    for (int w = 1; w < 8; w++) m8 = fmaxf(m8, red[w]);
    __syncthreads();

    float sum = 0.f;
    #pragma unroll
    for (int t = 0; t < 8; t++) { v[t] = __expf(v[t] - m8); sum += v[t]; }
    #pragma unroll
    for (int o = 16; o; o >>= 1) sum += __shfl_xor_sync(0xffffffffu, sum, o);
    if ((tid & 31) == 0) red[tid >> 5] = sum;
    __syncthreads();
    float s8 = 0.f;
    #pragma unroll
    for (int w = 0; w < 8; w++) s8 += red[w];
    const float inv = 1.f / s8;

    #pragma unroll
    for (int t = 0; t < 8; t++) {
        float p = v[t] * inv;
        __nv_bfloat16 h = __float2bfloat16(p);
        size_t idx = (size_t)row * NS + tid + t*256;
        g_phi[idx] = h;
        g_plo[idx] = __float2bfloat16(p - __bfloat162float(h));
    }
}

// ---------------- PV: per (b,h) 2048x64x2048 -> ao (bf16 hi/lo) ------------
__global__ __launch_bounds__(256) void k_pv_mma() {
    extern __shared__ char dsm[];
    const int bh = blockIdx.z, q0 = blockIdx.y * 128;
    const size_t offA = ((size_t)bh*NS + q0) * NS;
    const size_t offB = (size_t)bh * DH * NS;
    float acc[32];
    hmma_core<64, 32, 32>(g_phi + offA, g_plo + offA, NS,
                          g_vthi + offB, g_vtlo + offB, NS, NS, dsm, acc);
    const int lane = threadIdx.x & 31, w = threadIdx.x >> 5;
    const int wm = w >> 1, wn = w & 1;
    const int b = bh >> 4, h = bh & 15;
    #pragma unroll
    for (int mt = 0; mt < 2; mt++)
        #pragma unroll
        for (int nt = 0; nt < 4; nt++)
            #pragma unroll
            for (int i = 0; i < 4; i++) {
                int row = wm*32 + mt*16 + (lane >> 2) + (i >> 1)*8;
                int col = wn*32 + nt*8 + (lane & 3)*2 + (i & 1);
                int sq = q0 + row;
                float vv = acc[(mt*4 + nt)*4 + i];
                size_t o = ((size_t)b*NS + sq)*ND + h*DH + col;
                __nv_bfloat16 hh = __float2bfloat16(vv);
                g_aohi[o] = hh;
                g_aolo[o] = __float2bfloat16(vv - __bfloat162float(hh));
            }
}

// ---------------- output projection -> d_out -------------------------------
__global__ __launch_bounds__(256) void k_out_mma(const float* __restrict__ bo,
                                                 float* __restrict__ out) {
    extern __shared__ char dsm[];
    const int brow = blockIdx.y * 128, bcol = blockIdx.x * 128;
    const __nv_bfloat16* wh = g_wthi + (size_t)3*ND*ND + (size_t)bcol*ND;
    const __nv_bfloat16* wl = g_wtlo + (size_t)3*ND*ND + (size_t)bcol*ND;
    float acc[64];
    hmma_core<128, 64, 32>(g_aohi + (size_t)brow*ND, g_aolo + (size_t)brow*ND, ND,
                           wh, wl, ND, ND, dsm, acc);
    const int lane = threadIdx.x & 31, w = threadIdx.x >> 5;
    const int wm = w >> 2, wn = w & 3;
    #pragma unroll
    for (int mt = 0; mt < 4; mt++)
        #pragma unroll
        for (int nt = 0; nt < 4; nt++) {
            int row = brow + wm*64 + mt*16 + (lane >> 2);
            int col = bcol + wn*32 + nt*8 + (lane & 3)*2;
            float* c = acc + (mt*4 + nt)*4;
            float* o0 = out + (size_t)row*ND + col;
            *(float2*)o0 = make_float2(c[0] + bo[col], c[1] + bo[col + 1]);
            *(float2*)(o0 + 8*(size_t)ND) = make_float2(c[2] + bo[col], c[3] + bo[col + 1]);
        }
}

// ---------------------------------------------------------------------------
#define SMEM_N128 (4*128*STRB)              // 73728: Ahi/Alo 128 + Bhi/Blo 128
#define SMEM_N64  (2*128*STRB + 2*64*STRB)  // 55296

extern "C" void kernel_launch(void* const* d_in, const int* in_sizes, int n_in,
                              void* d_out, int out_size) {
    const float* x    = (const float*)d_in[0];
    const int*   mask = (const int*)  d_in[1];
    const float* wq   = (const float*)d_in[2];
    const float* bq   = (const float*)d_in[3];
    const float* wk   = (const float*)d_in[4];
    const float* bk   = (const float*)d_in[5];
    const float* wv   = (const float*)d_in[6];
    const float* bv   = (const float*)d_in[7];
    const float* wo   = (const float*)d_in[8];
    const float* bo   = (const float*)d_in[9];
    float* out = (float*)d_out;

    cudaFuncSetAttribute(k_qkv_mma, cudaFuncAttributeMaxDynamicSharedMemorySize, SMEM_N128);
    cudaFuncSetAttribute(k_qkt_mma, cudaFuncAttributeMaxDynamicSharedMemorySize, SMEM_N128);
    cudaFuncSetAttribute(k_pv_mma,  cudaFuncAttributeMaxDynamicSharedMemorySize, SMEM_N64);
    cudaFuncSetAttribute(k_out_mma, cudaFuncAttributeMaxDynamicSharedMemorySize, SMEM_N128);

    // 1. input + weight conversions, RoPE table
    k_convert_x<<<NM*ND/256, 256>>>(x);
    k_wtrans<<<dim3(32, 32, 4), dim3(32, 8)>>>(wq, wk, wv, wo);
    k_rope_tab<<<NS*32/256, 256>>>();

    // 2. QKV projections (HMMA) with fused bias + RoPE + split + V^T
    k_qkv_mma<<<dim3(ND/128, NM/128, 3), 256, SMEM_N128>>>(bq, bk, bv);

    // 3. attention on tensor cores (materialized)
    k_qkt_mma<<<dim3(NS/128, NS/128, BHT), 256, SMEM_N128>>>();
    k_softmax<<<BHT*NS, 256>>>(mask);
    k_pv_mma<<<dim3(1, NS/128, BHT), 256, SMEM_N64>>>();

    // 4. output projection
    k_out_mma<<<dim3(ND/128, NM/128, 1), 256, SMEM_N128>>>(bo, out);
}

// round 15
// speedup vs baseline: 3.2005x; 1.3218x over previous
#include <cuda_runtime.h>
#include <cuda_bf16.h>
#include <cstdint>
#include <math.h>

#define NB 2
#define NS 2048
#define ND 1024
#define NH 16
#define DH 64
#define NM (NB*NS)     // 4096
#define BHT (NB*NH)    // 32

// ---------------- scratch (__device__ globals; allocation-free rule) -------
__device__ __nv_bfloat16 g_xhi[NM*ND],  g_xlo[NM*ND];
__device__ __nv_bfloat16 g_wthi[4*ND*ND], g_wtlo[4*ND*ND];     // W^T per weight
__device__ __nv_bfloat16 g_qhi[BHT*NS*DH], g_qlo[BHT*NS*DH];
__device__ __nv_bfloat16 g_khi[BHT*NS*DH], g_klo[BHT*NS*DH];
__device__ __nv_bfloat16 g_vthi[BHT*DH*NS], g_vtlo[BHT*DH*NS]; // V^T per (b,h)
__device__ __nv_bfloat16 g_aohi[NM*ND], g_aolo[NM*ND];
__device__ float g_rc[NS*32], g_rs[NS*32];                     // RoPE cos/sin table

// ---------------- warp MMA helpers (sm_80+ mma.sync) -----------------------
__device__ __forceinline__ uint32_t smem_u32(const void* p) {
    uint32_t a;
    asm("{ .reg .u64 t; cvta.to.shared.u64 t, %1; cvt.u32.u64 %0, t; }" : "=r"(a) : "l"(p));
    return a;
}
#define LDSM4(r, a) \
    asm volatile("ldmatrix.sync.aligned.m8n8.x4.shared.b16 {%0,%1,%2,%3}, [%4];" \
        : "=r"((r)[0]), "=r"((r)[1]), "=r"((r)[2]), "=r"((r)[3]) : "r"(a))

__device__ __forceinline__ void mma16816(float* c, const uint32_t* a, const uint32_t* b) {
    asm volatile(
        "mma.sync.aligned.m16n8k16.row.col.f32.bf16.bf16.f32 "
        "{%0,%1,%2,%3}, {%4,%5,%6,%7}, {%8,%9}, {%0,%1,%2,%3};"
        : "+f"(c[0]), "+f"(c[1]), "+f"(c[2]), "+f"(c[3])
        : "r"(a[0]), "r"(a[1]), "r"(a[2]), "r"(a[3]), "r"(b[0]), "r"(b[1]));
}
// pack two f32 -> bf16x2 (lo = p0, hi = p1)
__device__ __forceinline__ uint32_t pack_bf2(float p0, float p1) {
    uint32_t r;
    asm("cvt.rn.bf16x2.f32 %0, %1, %2;" : "=r"(r) : "f"(p1), "f"(p0));
    return r;
}

// ---------------- hi/lo bf16 pair GEMM core (HMMA) --------------------------
#define STRH 72                 // smem row stride in halves (144B, conflict-free)
#define STRB 144
template<int NT, int WM, int WN>
__device__ __forceinline__ void hmma_core(
    const __nv_bfloat16* __restrict__ Ahi, const __nv_bfloat16* __restrict__ Alo, int lda,
    const __nv_bfloat16* __restrict__ Bhi, const __nv_bfloat16* __restrict__ Blo, int ldb,
    int ktot, char* dsm, float* acc)
{
    constexpr int KC   = 64;
    constexpr int A_SZ = 128*STRB;
    constexpr int B_SZ = NT*STRB;
    constexpr int OFF_ALO = A_SZ, OFF_BHI = 2*A_SZ, OFF_BLO = 2*A_SZ + B_SZ;
    constexpr int WARPS_N = NT/WN;
    constexpr int MT = WM/16, NTT = WN/8;

    const int tid = threadIdx.x, lane = tid & 31, w = tid >> 5;
    const int wm = w / WARPS_N, wn = w % WARPS_N;
    const uint32_t sb = smem_u32(dsm);

    #pragma unroll
    for (int i = 0; i < MT*NTT*4; i++) acc[i] = 0.f;

    const uint32_t aro = (uint32_t)(wm*WM + (lane & 15)) * STRB + (lane >> 4) * 16;
    const uint32_t bro = (uint32_t)(wn*WN + (lane & 7) + (lane >> 4) * 8) * STRB
                       + ((lane >> 3) & 1) * 16;

    for (int k0 = 0; k0 < ktot; k0 += KC) {
        for (int i = tid; i < 128*8; i += 256) {
            int r = i >> 3, u = i & 7;
            int so = r*STRB + u*16;
            const size_t off = (size_t)r*lda + k0 + u*8;
            *(uint4*)(dsm + so)           = *(const uint4*)(Ahi + off);
            *(uint4*)(dsm + OFF_ALO + so) = *(const uint4*)(Alo + off);
        }
        for (int i = tid; i < NT*8; i += 256) {
            int r = i >> 3, u = i & 7;
            int so = r*STRB + u*16;
            const size_t off = (size_t)r*ldb + k0 + u*8;
            *(uint4*)(dsm + OFF_BHI + so) = *(const uint4*)(Bhi + off);
            *(uint4*)(dsm + OFF_BLO + so) = *(const uint4*)(Blo + off);
        }
        __syncthreads();

        #pragma unroll
        for (int ks = 0; ks < KC/16; ks++) {
            uint32_t ah[MT][4], al[MT][4];
            #pragma unroll
            for (int mt = 0; mt < MT; mt++) {
                uint32_t ro = aro + (uint32_t)mt*16*STRB + ks*32;
                LDSM4(ah[mt], sb + ro);
                LDSM4(al[mt], sb + OFF_ALO + ro);
            }
            uint32_t bh[NTT][2], bl[NTT][2];
            #pragma unroll
            for (int np = 0; np < NTT/2; np++) {
                uint32_t ro = bro + (uint32_t)np*16*STRB + ks*32;
                uint32_t t4[4];
                LDSM4(t4, sb + OFF_BHI + ro);
                bh[2*np][0] = t4[0]; bh[2*np][1] = t4[1];
                bh[2*np+1][0] = t4[2]; bh[2*np+1][1] = t4[3];
                LDSM4(t4, sb + OFF_BLO + ro);
                bl[2*np][0] = t4[0]; bl[2*np][1] = t4[1];
                bl[2*np+1][0] = t4[2]; bl[2*np+1][1] = t4[3];
            }
            #pragma unroll
            for (int mt = 0; mt < MT; mt++)
                #pragma unroll
                for (int nt = 0; nt < NTT; nt++) {
                    float* c = acc + (mt*NTT + nt)*4;
                    mma16816(c, ah[mt], bh[nt]);   // hi*hi
                    mma16816(c, ah[mt], bl[nt]);   // hi*lo
                    mma16816(c, al[mt], bh[nt]);   // lo*hi
                }
        }
        __syncthreads();
    }
}

// ---------------- RoPE cos/sin table ---------------------------------------
__global__ void k_rope_tab() {
    int i = blockIdx.x * 256 + threadIdx.x;
    int t = i & 31, s = i >> 5;
    double inv = pow(10000.0, -(double)t / 32.0);
    float a = (float)((double)s * inv);
    g_rc[i] = cosf(a);
    g_rs[i] = sinf(a);
}

// ---------------- conversions ----------------------------------------------
__global__ void k_convert_x(const float* __restrict__ x) {
    int i = blockIdx.x * 256 + threadIdx.x;
    float v = x[i];
    __nv_bfloat16 h = __float2bfloat16(v);
    g_xhi[i] = h;
    g_xlo[i] = __float2bfloat16(v - __bfloat162float(h));
}

__global__ void k_wtrans(const float* __restrict__ wq, const float* __restrict__ wk,
                         const float* __restrict__ wv, const float* __restrict__ wo) {
    __shared__ float t[32][33];
    const int z = blockIdx.z;
    const float* w = (z == 0) ? wq : (z == 1) ? wk : (z == 2) ? wv : wo;
    __nv_bfloat16* oh = g_wthi + (size_t)z*ND*ND;
    __nv_bfloat16* ol = g_wtlo + (size_t)z*ND*ND;
    int bx = blockIdx.x * 32, by = blockIdx.y * 32;
    int tx = threadIdx.x, ty = threadIdx.y;
    #pragma unroll
    for (int j = 0; j < 4; j++)
        t[ty + j*8][tx] = w[(size_t)(by + ty + j*8)*ND + bx + tx];
    __syncthreads();
    #pragma unroll
    for (int j = 0; j < 4; j++) {
        float v = t[tx][ty + j*8];
        int n = bx + ty + j*8, kk = by + tx;
        __nv_bfloat16 h = __float2bfloat16(v);
        oh[(size_t)n*ND + kk] = h;
        ol[(size_t)n*ND + kk] = __float2bfloat16(v - __bfloat162float(h));
    }
}

// ---------------- QKV projection + fused bias/RoPE/split/V^T ---------------
__global__ __launch_bounds__(256) void k_qkv_mma(
    const float* __restrict__ bq, const float* __restrict__ bk, const float* __restrict__ bv)
{
    extern __shared__ char dsm[];
    const int z = blockIdx.z;
    const __nv_bfloat16* wh = g_wthi + (size_t)z*ND*ND;
    const __nv_bfloat16* wl = g_wtlo + (size_t)z*ND*ND;
    const float* bias = (z == 0) ? bq : (z == 1) ? bk : bv;

    const int brow = blockIdx.y * 128, bcol = blockIdx.x * 128;
    float acc[64];
    hmma_core<128, 64, 32>(g_xhi + (size_t)brow*ND, g_xlo + (size_t)brow*ND, ND,
                           wh + (size_t)bcol*ND,   wl + (size_t)bcol*ND,   ND,
                           ND, dsm, acc);
    const int tid = threadIdx.x, lane = tid & 31, w = tid >> 5;
    const int wm = w >> 2, wn = w & 3;
    float* smf = (float*)dsm;
    #pragma unroll
    for (int mt = 0; mt < 4; mt++)
        #pragma unroll
        for (int nt = 0; nt < 4; nt++)
            #pragma unroll
            for (int i = 0; i < 4; i++) {
                int row = wm*64 + mt*16 + (lane >> 2) + (i >> 1)*8;
                int col = wn*32 + nt*8 + (lane & 3)*2 + (i & 1);
                smf[row*129 + col] = acc[(mt*4 + nt)*4 + i] + bias[bcol + col];
            }
    __syncthreads();

    const int b  = brow >> 11;
    const int s0 = brow & (NS - 1);
    if (z < 2) {
        __nv_bfloat16* oh = (z == 0) ? g_qhi : g_khi;
        __nv_bfloat16* ol = (z == 0) ? g_qlo : g_klo;
        for (int i = tid; i < 128*64; i += 256) {
            int d  = i & 31;
            int hl = (i >> 5) & 1;
            int r  = i >> 6;
            int h  = (bcol >> 6) + hl;
            int s  = s0 + r;
            float x1 = smf[r*129 + hl*64 + d];
            float x2 = smf[r*129 + hl*64 + d + 32];
            int t1 = d >> 1;
            float c1 = g_rc[s*32 + t1],      s1 = g_rs[s*32 + t1];
            float c2 = g_rc[s*32 + t1 + 16], s2 = g_rs[s*32 + t1 + 16];
            float y1 = x1 * c1 - x2 * s1;
            float y2 = x2 * c2 + x1 * s2;
            size_t base = (((size_t)b*NH + h)*NS + s)*DH;
            __nv_bfloat16 h1 = __float2bfloat16(y1);
            oh[base + d]      = h1;
            ol[base + d]      = __float2bfloat16(y1 - __bfloat162float(h1));
            __nv_bfloat16 h2 = __float2bfloat16(y2);
            oh[base + d + 32] = h2;
            ol[base + d + 32] = __float2bfloat16(y2 - __bfloat162float(h2));
        }
    } else {
        for (int i = tid; i < 128*128; i += 256) {
            int r = i & 127, c = i >> 7;
            int h = (bcol >> 6) + (c >> 6), d = c & 63;
            int s = s0 + r;
            float v = smf[r*129 + c];
            size_t o = (((size_t)b*NH + h)*DH + d)*NS + s;
            __nv_bfloat16 hh = __float2bfloat16(v);
            g_vthi[o] = hh;
            g_vtlo[o] = __float2bfloat16(v - __bfloat162float(hh));
        }
    }
}

// ---------------- fused flash attention ------------------------------------
// block = (q-tile 128, bh). 8 warps x 16 q-rows. KV tiles of 64.
// S/P per warp 16x64 in regs; O 16x64 fp32 acc; Q A-frags preloaded.
#define ATSZ (64*STRB)   // 9216 per tile buffer
#define ATT_SMEM (4*ATSZ + 256)
__global__ __launch_bounds__(256) void k_attn(const int* __restrict__ mask) {
    extern __shared__ char dsm[];
    float* s_mask = (float*)(dsm + 4*ATSZ);
    const int tid = threadIdx.x, lane = tid & 31, w = tid >> 5;
    const int q0 = blockIdx.x * 128, bh = blockIdx.y;
    const int b = bh >> 4, h = bh & 15;
    const uint32_t sb = smem_u32(dsm);

    // ---- stage Q tile (128 x 64, hi at 0, lo at 2*ATSZ) and grab A-frags
    const __nv_bfloat16* Qh = g_qhi + ((size_t)bh*NS + q0)*DH;
    const __nv_bfloat16* Ql = g_qlo + ((size_t)bh*NS + q0)*DH;
    for (int i = tid; i < 128*8; i += 256) {
        int r = i >> 3, u = i & 7;
        int so = r*STRB + u*16;
        *(uint4*)(dsm + so)          = *(const uint4*)(Qh + (size_t)r*DH + u*8);
        *(uint4*)(dsm + 2*ATSZ + so) = *(const uint4*)(Ql + (size_t)r*DH + u*8);
    }
    __syncthreads();
    uint32_t qh[4][4], ql[4][4];
    const uint32_t aro = (uint32_t)(w*16 + (lane & 15))*STRB + (lane >> 4)*16;
    #pragma unroll
    for (int g = 0; g < 4; g++) {
        LDSM4(qh[g], sb + aro + g*32);
        LDSM4(ql[g], sb + 2*ATSZ + aro + g*32);
    }
    __syncthreads();   // done with Q staging; buffers become K/V

    float o[8][4];
    #pragma unroll
    for (int nf = 0; nf < 8; nf++)
        #pragma unroll
        for (int j = 0; j < 4; j++) o[nf][j] = 0.f;
    float m[2] = {-1e30f, -1e30f}, l[2] = {0.f, 0.f};

    const __nv_bfloat16* Kh = g_khi + (size_t)bh*NS*DH;
    const __nv_bfloat16* Kl = g_klo + (size_t)bh*NS*DH;
    const __nv_bfloat16* Vh = g_vthi + (size_t)bh*DH*NS;
    const __nv_bfloat16* Vl = g_vtlo + (size_t)bh*DH*NS;
    const uint32_t bro = (uint32_t)((lane & 7) + ((lane >> 4) << 3))*STRB
                       + ((lane >> 3) & 1)*16;

    for (int kt = 0; kt < NS/64; kt++) {
        const int k0 = kt*64;
        // ---- load K (kv x d) and V (d x kv) tiles, hi/lo
        for (int i = tid; i < 64*8; i += 256) {
            int r = i >> 3, u = i & 7;
            int so = r*STRB + u*16;
            *(uint4*)(dsm + so)          = *(const uint4*)(Kh + (size_t)(k0 + r)*DH + u*8);
            *(uint4*)(dsm + ATSZ + so)   = *(const uint4*)(Kl + (size_t)(k0 + r)*DH + u*8);
            *(uint4*)(dsm + 2*ATSZ + so) = *(const uint4*)(Vh + (size_t)r*NS + k0 + u*8);
            *(uint4*)(dsm + 3*ATSZ + so) = *(const uint4*)(Vl + (size_t)r*NS + k0 + u*8);
        }
        if (tid < 64) s_mask[tid] = -1e9f * (float)mask[b*NS + k0 + tid];
        __syncthreads();

        // ---- S = Q @ K^T  (16 x 64 per warp, 3-term hi/lo)
        float s[8][4];
        #pragma unroll
        for (int nf = 0; nf < 8; nf++)
            #pragma unroll
            for (int j = 0; j < 4; j++) s[nf][j] = 0.f;
        #pragma unroll
        for (int g = 0; g < 4; g++)
            #pragma unroll
            for (int np = 0; np < 4; np++) {
                uint32_t ro = bro + (uint32_t)np*16*STRB + g*32;
                uint32_t th[4], tl[4];
                LDSM4(th, sb + ro);
                LDSM4(tl, sb + ATSZ + ro);
                mma16816(s[2*np],     qh[g], th);
                mma16816(s[2*np],     qh[g], tl);
                mma16816(s[2*np],     ql[g], th);
                mma16816(s[2*np + 1], qh[g], th + 2);
                mma16816(s[2*np + 1], qh[g], tl + 2);
                mma16816(s[2*np + 1], ql[g], th + 2);
            }

        // ---- online softmax (rows: rg=0 -> lane/4, rg=1 -> +8)
        #pragma unroll
        for (int rg = 0; rg < 2; rg++) {
            float mx = -1e30f;
            #pragma unroll
            for (int nf = 0; nf < 8; nf++)
                #pragma unroll
                for (int j = 0; j < 2; j++) {
                    int idx = rg*2 + j;
                    s[nf][idx] = s[nf][idx]*0.125f + s_mask[nf*8 + (lane & 3)*2 + j];
                    mx = fmaxf(mx, s[nf][idx]);
                }
            mx = fmaxf(mx, __shfl_xor_sync(0xffffffffu, mx, 1));
            mx = fmaxf(mx, __shfl_xor_sync(0xffffffffu, mx, 2));
            float mn = fmaxf(m[rg], mx);
            float al = __expf(m[rg] - mn);
            float ls = 0.f;
            #pragma unroll
            for (int nf = 0; nf < 8; nf++)
                #pragma unroll
                for (int j = 0; j < 2; j++) {
                    int idx = rg*2 + j;
                    float p = __expf(s[nf][idx] - mn);
                    s[nf][idx] = p;
                    ls += p;
                }
            ls += __shfl_xor_sync(0xffffffffu, ls, 1);
            ls += __shfl_xor_sync(0xffffffffu, ls, 2);
            l[rg] = l[rg]*al + ls;
            m[rg] = mn;
            #pragma unroll
            for (int nf = 0; nf < 8; nf++)
                #pragma unroll
                for (int j = 0; j < 2; j++) o[nf][rg*2 + j] *= al;
        }

        // ---- O += P @ V  (P from S regs via C->A layout identity)
        #pragma unroll
        for (int g2 = 0; g2 < 4; g2++) {
            uint32_t ph[4], pl[4];
            #pragma unroll
            for (int half = 0; half < 2; half++) {      // nfrag 2*g2 + half
                float* sp = s[2*g2 + half];
                float r0 = sp[0] - __bfloat162float(__float2bfloat16(sp[0]));
                float r1 = sp[1] - __bfloat162float(__float2bfloat16(sp[1]));
                float r2 = sp[2] - __bfloat162float(__float2bfloat16(sp[2]));
                float r3 = sp[3] - __bfloat162float(__float2bfloat16(sp[3]));
                ph[2*half]     = pack_bf2(sp[0], sp[1]);
                ph[2*half + 1] = pack_bf2(sp[2], sp[3]);
                pl[2*half]     = pack_bf2(r0, r1);
                pl[2*half + 1] = pack_bf2(r2, r3);
            }
            #pragma unroll
            for (int np = 0; np < 4; np++) {
                uint32_t ro = bro + (uint32_t)np*16*STRB + g2*32;
                uint32_t th[4], tl[4];
                LDSM4(th, sb + 2*ATSZ + ro);
                LDSM4(tl, sb + 3*ATSZ + ro);
                mma16816(o[2*np],     ph, th);
                mma16816(o[2*np],     ph, tl);
                mma16816(o[2*np],     pl, th);
                mma16816(o[2*np + 1], ph, th + 2);
                mma16816(o[2*np + 1], ph, tl + 2);
                mma16816(o[2*np + 1], pl, th + 2);
            }
        }
        __syncthreads();   // everyone done reading K/V before next tile load
    }

    // ---- epilogue: normalize, write bf16 hi/lo ao
    float inv[2] = {1.f / l[0], 1.f / l[1]};
    #pragma unroll
    for (int nf = 0; nf < 8; nf++)
        #pragma unroll
        for (int rg = 0; rg < 2; rg++)
            #pragma unroll
            for (int j = 0; j < 2; j++) {
                int sq = q0 + w*16 + (lane >> 2) + rg*8;
                int d  = nf*8 + (lane & 3)*2 + j;
                float v = o[nf][rg*2 + j] * inv[rg];
                size_t off = ((size_t)b*NS + sq)*ND + h*DH + d;
                __nv_bfloat16 hh = __float2bfloat16(v);
                g_aohi[off] = hh;
                g_aolo[off] = __float2bfloat16(v - __bfloat162float(hh));
            }
}

// ---------------- output projection -> d_out -------------------------------
__global__ __launch_bounds__(256) void k_out_mma(const float* __restrict__ bo,
                                                 float* __restrict__ out) {
    extern __shared__ char dsm[];
    const int brow = blockIdx.y * 128, bcol = blockIdx.x * 128;
    const __nv_bfloat16* wh = g_wthi + (size_t)3*ND*ND + (size_t)bcol*ND;
    const __nv_bfloat16* wl = g_wtlo + (size_t)3*ND*ND + (size_t)bcol*ND;
    float acc[64];
    hmma_core<128, 64, 32>(g_aohi + (size_t)brow*ND, g_aolo + (size_t)brow*ND, ND,
                           wh, wl, ND, ND, dsm, acc);
    const int lane = threadIdx.x & 31, w = threadIdx.x >> 5;
    const int wm = w >> 2, wn = w & 3;
    #pragma unroll
    for (int mt = 0; mt < 4; mt++)
        #pragma unroll
        for (int nt = 0; nt < 4; nt++) {
            int row = brow + wm*64 + mt*16 + (lane >> 2);
            int col = bcol + wn*32 + nt*8 + (lane & 3)*2;
            float* c = acc + (mt*4 + nt)*4;
            float* o0 = out + (size_t)row*ND + col;
            *(float2*)o0 = make_float2(c[0] + bo[col], c[1] + bo[col + 1]);
            *(float2*)(o0 + 8*(size_t)ND) = make_float2(c[2] + bo[col], c[3] + bo[col + 1]);
        }
}

// ---------------------------------------------------------------------------
#define SMEM_N128 (4*128*STRB)              // 73728

extern "C" void kernel_launch(void* const* d_in, const int* in_sizes, int n_in,
                              void* d_out, int out_size) {
    const float* x    = (const float*)d_in[0];
    const int*   mask = (const int*)  d_in[1];
    const float* wq   = (const float*)d_in[2];
    const float* bq   = (const float*)d_in[3];
    const float* wk   = (const float*)d_in[4];
    const float* bk   = (const float*)d_in[5];
    const float* wv   = (const float*)d_in[6];
    const float* bv   = (const float*)d_in[7];
    const float* wo   = (const float*)d_in[8];
    const float* bo   = (const float*)d_in[9];
    float* out = (float*)d_out;

    cudaFuncSetAttribute(k_qkv_mma, cudaFuncAttributeMaxDynamicSharedMemorySize, SMEM_N128);
    cudaFuncSetAttribute(k_attn,    cudaFuncAttributeMaxDynamicSharedMemorySize, ATT_SMEM);
    cudaFuncSetAttribute(k_out_mma, cudaFuncAttributeMaxDynamicSharedMemorySize, SMEM_N128);

    // 1. input + weight conversions, RoPE table
    k_convert_x<<<NM*ND/256, 256>>>(x);
    k_wtrans<<<dim3(32, 32, 4), dim3(32, 8)>>>(wq, wk, wv, wo);
    k_rope_tab<<<NS*32/256, 256>>>();

    // 2. QKV projections (HMMA) with fused bias + RoPE + split + V^T
    k_qkv_mma<<<dim3(ND/128, NM/128, 3), 256, SMEM_N128>>>(bq, bk, bv);

    // 3. fused flash attention (QK^T + softmax + PV in one kernel)
    k_attn<<<dim3(NS/128, BHT), 256, ATT_SMEM>>>(mask);

    // 4. output projection
    k_out_mma<<<dim3(ND/128, NM/128, 1), 256, SMEM_N128>>>(bo, out);
}

// round 16
// speedup vs baseline: 3.5172x; 1.0990x over previous
#include <cuda_runtime.h>
#include <cuda_bf16.h>
#include <cstdint>
#include <math.h>

#define NB 2
#define NS 2048
#define ND 1024
#define NH 16
#define DH 64
#define NM (NB*NS)     // 4096
#define BHT (NB*NH)    // 32

// ---------------- scratch (__device__ globals; allocation-free rule) -------
__device__ __nv_bfloat16 g_xhi[NM*ND],  g_xlo[NM*ND];
__device__ __nv_bfloat16 g_wthi[4*ND*ND], g_wtlo[4*ND*ND];     // W^T per weight
__device__ __nv_bfloat16 g_qhi[BHT*NS*DH], g_qlo[BHT*NS*DH];
__device__ __nv_bfloat16 g_khi[BHT*NS*DH], g_klo[BHT*NS*DH];
__device__ __nv_bfloat16 g_vthi[BHT*DH*NS], g_vtlo[BHT*DH*NS]; // V^T per (b,h)
__device__ __nv_bfloat16 g_aohi[NM*ND], g_aolo[NM*ND];
__device__ float g_rc[NS*32], g_rs[NS*32];                     // RoPE cos/sin table

// ---------------- warp MMA helpers (sm_80+ mma.sync) -----------------------
__device__ __forceinline__ uint32_t smem_u32(const void* p) {
    uint32_t a;
    asm("{ .reg .u64 t; cvta.to.shared.u64 t, %1; cvt.u32.u64 %0, t; }" : "=r"(a) : "l"(p));
    return a;
}
#define LDSM4(r, a) \
    asm volatile("ldmatrix.sync.aligned.m8n8.x4.shared.b16 {%0,%1,%2,%3}, [%4];" \
        : "=r"((r)[0]), "=r"((r)[1]), "=r"((r)[2]), "=r"((r)[3]) : "r"(a))

__device__ __forceinline__ void mma16816(float* c, const uint32_t* a, const uint32_t* b) {
    asm volatile(
        "mma.sync.aligned.m16n8k16.row.col.f32.bf16.bf16.f32 "
        "{%0,%1,%2,%3}, {%4,%5,%6,%7}, {%8,%9}, {%0,%1,%2,%3};"
        : "+f"(c[0]), "+f"(c[1]), "+f"(c[2]), "+f"(c[3])
        : "r"(a[0]), "r"(a[1]), "r"(a[2]), "r"(a[3]), "r"(b[0]), "r"(b[1]));
}
__device__ __forceinline__ uint32_t pack_bf2(float p0, float p1) {
    uint32_t r;
    asm("cvt.rn.bf16x2.f32 %0, %1, %2;" : "=r"(r) : "f"(p1), "f"(p0));
    return r;
}
// cp.async 16B
#define CPA16(smaddr, gptr) \
    asm volatile("cp.async.cg.shared.global [%0], [%1], 16;" :: "r"(smaddr), "l"(gptr))
#define CP_COMMIT() asm volatile("cp.async.commit_group;" ::: "memory")
#define CP_WAIT1()  asm volatile("cp.async.wait_group 1;" ::: "memory")

// ---------------- hi/lo bf16 pair GEMM core (HMMA, cp.async 2-stage) --------
#define STRH 72                 // smem row stride in halves (144B, conflict-free)
#define STRB 144

template<int NT>
__device__ __forceinline__ void gemm_issue(
    uint32_t stb,
    const __nv_bfloat16* __restrict__ Ahi, const __nv_bfloat16* __restrict__ Alo, int lda,
    const __nv_bfloat16* __restrict__ Bhi, const __nv_bfloat16* __restrict__ Blo, int ldb,
    int k0, int tid)
{
    constexpr int A_SZ = 128*STRB, B_SZ = NT*STRB;
    constexpr int OFF_ALO = A_SZ, OFF_BHI = 2*A_SZ, OFF_BLO = 2*A_SZ + B_SZ;
    for (int i = tid; i < 128*8; i += 256) {
        int r = i >> 3, u = i & 7;
        uint32_t so = stb + r*STRB + u*16;
        const size_t off = (size_t)r*lda + k0 + u*8;
        CPA16(so,           Ahi + off);
        CPA16(so + OFF_ALO, Alo + off);
    }
    for (int i = tid; i < NT*8; i += 256) {
        int r = i >> 3, u = i & 7;
        uint32_t so = stb + r*STRB + u*16;
        const size_t off = (size_t)r*ldb + k0 + u*8;
        CPA16(so + OFF_BHI, Bhi + off);
        CPA16(so + OFF_BLO, Blo + off);
    }
}

template<int NT, int WM, int WN>
__device__ __forceinline__ void hmma_core(
    const __nv_bfloat16* __restrict__ Ahi, const __nv_bfloat16* __restrict__ Alo, int lda,
    const __nv_bfloat16* __restrict__ Bhi, const __nv_bfloat16* __restrict__ Blo, int ldb,
    int ktot, char* dsm, float* acc)
{
    constexpr int KC   = 64;
    constexpr int A_SZ = 128*STRB;
    constexpr int B_SZ = NT*STRB;
    constexpr int OFF_ALO = A_SZ, OFF_BHI = 2*A_SZ, OFF_BLO = 2*A_SZ + B_SZ;
    constexpr int STAGE = 2*A_SZ + 2*B_SZ;
    constexpr int WARPS_N = NT/WN;
    constexpr int MT = WM/16, NTT = WN/8;

    const int tid = threadIdx.x, lane = tid & 31, w = tid >> 5;
    const int wm = w / WARPS_N, wn = w % WARPS_N;
    const uint32_t sb = smem_u32(dsm);

    #pragma unroll
    for (int i = 0; i < MT*NTT*4; i++) acc[i] = 0.f;

    const uint32_t aro = (uint32_t)(wm*WM + (lane & 15)) * STRB + (lane >> 4) * 16;
    const uint32_t bro = (uint32_t)(wn*WN + (lane & 7) + (lane >> 4) * 8) * STRB
                       + ((lane >> 3) & 1) * 16;

    const int nch = ktot / KC;
    gemm_issue<NT>(sb, Ahi, Alo, lda, Bhi, Blo, ldb, 0, tid);
    CP_COMMIT();

    for (int kc = 0; kc < nch; kc++) {
        const uint32_t stb = sb + (uint32_t)(kc & 1)*STAGE;
        if (kc + 1 < nch)
            gemm_issue<NT>(sb + (uint32_t)((kc + 1) & 1)*STAGE,
                           Ahi, Alo, lda, Bhi, Blo, ldb, (kc + 1)*KC, tid);
        CP_COMMIT();
        CP_WAIT1();
        __syncthreads();

        #pragma unroll
        for (int ks = 0; ks < KC/16; ks++) {
            uint32_t ah[MT][4], al[MT][4];
            #pragma unroll
            for (int mt = 0; mt < MT; mt++) {
                uint32_t ro = stb + aro + (uint32_t)mt*16*STRB + ks*32;
                LDSM4(ah[mt], ro);
                LDSM4(al[mt], ro + OFF_ALO);
            }
            uint32_t bh[NTT][2], bl[NTT][2];
            #pragma unroll
            for (int np = 0; np < NTT/2; np++) {
                uint32_t ro = stb + bro + (uint32_t)np*16*STRB + ks*32;
                uint32_t t4[4];
                LDSM4(t4, ro + OFF_BHI);
                bh[2*np][0] = t4[0]; bh[2*np][1] = t4[1];
                bh[2*np+1][0] = t4[2]; bh[2*np+1][1] = t4[3];
                LDSM4(t4, ro + OFF_BLO);
                bl[2*np][0] = t4[0]; bl[2*np][1] = t4[1];
                bl[2*np+1][0] = t4[2]; bl[2*np+1][1] = t4[3];
            }
            #pragma unroll
            for (int mt = 0; mt < MT; mt++)
                #pragma unroll
                for (int nt = 0; nt < NTT; nt++) {
                    float* c = acc + (mt*NTT + nt)*4;
                    mma16816(c, ah[mt], bh[nt]);   // hi*hi
                    mma16816(c, ah[mt], bl[nt]);   // hi*lo
                    mma16816(c, al[mt], bh[nt]);   // lo*hi
                }
        }
        __syncthreads();
    }
}

// ---------------- RoPE cos/sin table ---------------------------------------
__global__ void k_rope_tab() {
    int i = blockIdx.x * 256 + threadIdx.x;
    int t = i & 31, s = i >> 5;
    double inv = pow(10000.0, -(double)t / 32.0);
    float a = (float)((double)s * inv);
    g_rc[i] = cosf(a);
    g_rs[i] = sinf(a);
}

// ---------------- conversions ----------------------------------------------
__global__ void k_convert_x(const float* __restrict__ x) {
    int i = blockIdx.x * 256 + threadIdx.x;
    float v = x[i];
    __nv_bfloat16 h = __float2bfloat16(v);
    g_xhi[i] = h;
    g_xlo[i] = __float2bfloat16(v - __bfloat162float(h));
}

__global__ void k_wtrans(const float* __restrict__ wq, const float* __restrict__ wk,
                         const float* __restrict__ wv, const float* __restrict__ wo) {
    __shared__ float t[32][33];
    const int z = blockIdx.z;
    const float* w = (z == 0) ? wq : (z == 1) ? wk : (z == 2) ? wv : wo;
    __nv_bfloat16* oh = g_wthi + (size_t)z*ND*ND;
    __nv_bfloat16* ol = g_wtlo + (size_t)z*ND*ND;
    int bx = blockIdx.x * 32, by = blockIdx.y * 32;
    int tx = threadIdx.x, ty = threadIdx.y;
    #pragma unroll
    for (int j = 0; j < 4; j++)
        t[ty + j*8][tx] = w[(size_t)(by + ty + j*8)*ND + bx + tx];
    __syncthreads();
    #pragma unroll
    for (int j = 0; j < 4; j++) {
        float v = t[tx][ty + j*8];
        int n = bx + ty + j*8, kk = by + tx;
        __nv_bfloat16 h = __float2bfloat16(v);
        oh[(size_t)n*ND + kk] = h;
        ol[(size_t)n*ND + kk] = __float2bfloat16(v - __bfloat162float(h));
    }
}

// ---------------- QKV projection + fused bias/RoPE/split/V^T ---------------
__global__ __launch_bounds__(256) void k_qkv_mma(
    const float* __restrict__ bq, const float* __restrict__ bk, const float* __restrict__ bv)
{
    extern __shared__ char dsm[];
    const int z = blockIdx.z;
    const __nv_bfloat16* wh = g_wthi + (size_t)z*ND*ND;
    const __nv_bfloat16* wl = g_wtlo + (size_t)z*ND*ND;
    const float* bias = (z == 0) ? bq : (z == 1) ? bk : bv;

    const int brow = blockIdx.y * 128, bcol = blockIdx.x * 128;
    float acc[64];
    hmma_core<128, 64, 32>(g_xhi + (size_t)brow*ND, g_xlo + (size_t)brow*ND, ND,
                           wh + (size_t)bcol*ND,   wl + (size_t)bcol*ND,   ND,
                           ND, dsm, acc);
    const int tid = threadIdx.x, lane = tid & 31, w = tid >> 5;
    const int wm = w >> 2, wn = w & 3;
    float* smf = (float*)dsm;
    #pragma unroll
    for (int mt = 0; mt < 4; mt++)
        #pragma unroll
        for (int nt = 0; nt < 4; nt++)
            #pragma unroll
            for (int i = 0; i < 4; i++) {
                int row = wm*64 + mt*16 + (lane >> 2) + (i >> 1)*8;
                int col = wn*32 + nt*8 + (lane & 3)*2 + (i & 1);
                smf[row*129 + col] = acc[(mt*4 + nt)*4 + i] + bias[bcol + col];
            }
    __syncthreads();

    const int b  = brow >> 11;
    const int s0 = brow & (NS - 1);
    if (z < 2) {
        __nv_bfloat16* oh = (z == 0) ? g_qhi : g_khi;
        __nv_bfloat16* ol = (z == 0) ? g_qlo : g_klo;
        for (int i = tid; i < 128*64; i += 256) {
            int d  = i & 31;
            int hl = (i >> 5) & 1;
            int r  = i >> 6;
            int h  = (bcol >> 6) + hl;
            int s  = s0 + r;
            float x1 = smf[r*129 + hl*64 + d];
            float x2 = smf[r*129 + hl*64 + d + 32];
            int t1 = d >> 1;
            float c1 = g_rc[s*32 + t1],      s1 = g_rs[s*32 + t1];
            float c2 = g_rc[s*32 + t1 + 16], s2 = g_rs[s*32 + t1 + 16];
            float y1 = x1 * c1 - x2 * s1;
            float y2 = x2 * c2 + x1 * s2;
            size_t base = (((size_t)b*NH + h)*NS + s)*DH;
            __nv_bfloat16 h1 = __float2bfloat16(y1);
            oh[base + d]      = h1;
            ol[base + d]      = __float2bfloat16(y1 - __bfloat162float(h1));
            __nv_bfloat16 h2 = __float2bfloat16(y2);
            oh[base + d + 32] = h2;
            ol[base + d + 32] = __float2bfloat16(y2 - __bfloat162float(h2));
        }
    } else {
        for (int i = tid; i < 128*128; i += 256) {
            int r = i & 127, c = i >> 7;
            int h = (bcol >> 6) + (c >> 6), d = c & 63;
            int s = s0 + r;
            float v = smf[r*129 + c];
            size_t o = (((size_t)b*NH + h)*DH + d)*NS + s;
            __nv_bfloat16 hh = __float2bfloat16(v);
            g_vthi[o] = hh;
            g_vtlo[o] = __float2bfloat16(v - __bfloat162float(hh));
        }
    }
}

// ---------------- fused flash attention (cp.async 2-stage KV) ---------------
#define ATSZ (64*STRB)          // 9216 per buffer
#define ASTAGE (4*ATSZ)         // 36864 per stage (K hi/lo + V hi/lo)
#define ATT_SMEM (2*ASTAGE + NS*4)   // 81920

__device__ __forceinline__ void attn_issue(
    uint32_t stb,
    const __nv_bfloat16* __restrict__ Kh, const __nv_bfloat16* __restrict__ Kl,
    const __nv_bfloat16* __restrict__ Vh, const __nv_bfloat16* __restrict__ Vl,
    int k0, int tid)
{
    for (int i = tid; i < 64*8; i += 256) {
        int r = i >> 3, u = i & 7;
        uint32_t so = stb + r*STRB + u*16;
        CPA16(so,            Kh + (size_t)(k0 + r)*DH + u*8);
        CPA16(so + ATSZ,     Kl + (size_t)(k0 + r)*DH + u*8);
        CPA16(so + 2*ATSZ,   Vh + (size_t)r*NS + k0 + u*8);
        CPA16(so + 3*ATSZ,   Vl + (size_t)r*NS + k0 + u*8);
    }
}

__global__ __launch_bounds__(256) void k_attn(const int* __restrict__ mask) {
    extern __shared__ char dsm[];
    float* s_mask = (float*)(dsm + 2*ASTAGE);
    const int tid = threadIdx.x, lane = tid & 31, w = tid >> 5;
    const int q0 = blockIdx.x * 128, bh = blockIdx.y;
    const int b = bh >> 4, h = bh & 15;
    const uint32_t sb = smem_u32(dsm);

    // ---- full mask row once
    for (int i = tid; i < NS; i += 256) s_mask[i] = -1e9f * (float)mask[b*NS + i];

    // ---- stage Q tile (hi at 0, lo at ATSZ, inside stage 0) and grab A-frags
    const __nv_bfloat16* Qh = g_qhi + ((size_t)bh*NS + q0)*DH;
    const __nv_bfloat16* Ql = g_qlo + ((size_t)bh*NS + q0)*DH;
    for (int i = tid; i < 128*8; i += 256) {
        int r = i >> 3, u = i & 7;
        int so = (r & 63)*STRB + u*16 + (r >> 6)*(2*ATSZ);  // rows 64-127 -> stage1 area
        *(uint4*)(dsm + so)        = *(const uint4*)(Qh + (size_t)r*DH + u*8);
        *(uint4*)(dsm + ATSZ + so) = *(const uint4*)(Ql + (size_t)r*DH + u*8);
    }
    __syncthreads();
    uint32_t qh[4][4], ql[4][4];
    {
        int qr = w*16 + (lane & 15);   // 0..127
        const uint32_t aro = (uint32_t)(qr & 63)*STRB + (lane >> 4)*16 + (qr >> 6)*(2*ATSZ);
        #pragma unroll
        for (int g = 0; g < 4; g++) {
            LDSM4(qh[g], sb + aro + g*32);
            LDSM4(ql[g], sb + ATSZ + aro + g*32);
        }
    }
    __syncthreads();   // Q staging done; stages free for KV

    float o[8][4];
    #pragma unroll
    for (int nf = 0; nf < 8; nf++)
        #pragma unroll
        for (int j = 0; j < 4; j++) o[nf][j] = 0.f;
    float m[2] = {-1e30f, -1e30f}, l[2] = {0.f, 0.f};

    const __nv_bfloat16* Kh = g_khi + (size_t)bh*NS*DH;
    const __nv_bfloat16* Kl = g_klo + (size_t)bh*NS*DH;
    const __nv_bfloat16* Vh = g_vthi + (size_t)bh*DH*NS;
    const __nv_bfloat16* Vl = g_vtlo + (size_t)bh*DH*NS;
    const uint32_t bro = (uint32_t)((lane & 7) + ((lane >> 4) << 3))*STRB
                       + ((lane >> 3) & 1)*16;

    attn_issue(sb, Kh, Kl, Vh, Vl, 0, tid);
    CP_COMMIT();

    for (int kt = 0; kt < NS/64; kt++) {
        const int k0 = kt*64;
        const uint32_t stb = sb + (uint32_t)(kt & 1)*ASTAGE;
        if (kt + 1 < NS/64)
            attn_issue(sb + (uint32_t)((kt + 1) & 1)*ASTAGE, Kh, Kl, Vh, Vl, (kt + 1)*64, tid);
        CP_COMMIT();
        CP_WAIT1();
        __syncthreads();

        // ---- S = Q @ K^T
        float s[8][4];
        #pragma unroll
        for (int nf = 0; nf < 8; nf++)
            #pragma unroll
            for (int j = 0; j < 4; j++) s[nf][j] = 0.f;
        #pragma unroll
        for (int g = 0; g < 4; g++)
            #pragma unroll
            for (int np = 0; np < 4; np++) {
                uint32_t ro = stb + bro + (uint32_t)np*16*STRB + g*32;
                uint32_t th[4], tl[4];
                LDSM4(th, ro);
                LDSM4(tl, ro + ATSZ);
                mma16816(s[2*np],     qh[g], th);
                mma16816(s[2*np],     qh[g], tl);
                mma16816(s[2*np],     ql[g], th);
                mma16816(s[2*np + 1], qh[g], th + 2);
                mma16816(s[2*np + 1], qh[g], tl + 2);
                mma16816(s[2*np + 1], ql[g], th + 2);
            }

        // ---- online softmax
        #pragma unroll
        for (int rg = 0; rg < 2; rg++) {
            float mx = -1e30f;
            #pragma unroll
            for (int nf = 0; nf < 8; nf++)
                #pragma unroll
                for (int j = 0; j < 2; j++) {
                    int idx = rg*2 + j;
                    s[nf][idx] = s[nf][idx]*0.125f + s_mask[k0 + nf*8 + (lane & 3)*2 + j];
                    mx = fmaxf(mx, s[nf][idx]);
                }
            mx = fmaxf(mx, __shfl_xor_sync(0xffffffffu, mx, 1));
            mx = fmaxf(mx, __shfl_xor_sync(0xffffffffu, mx, 2));
            float mn = fmaxf(m[rg], mx);
            float al = __expf(m[rg] - mn);
            float ls = 0.f;
            #pragma unroll
            for (int nf = 0; nf < 8; nf++)
                #pragma unroll
                for (int j = 0; j < 2; j++) {
                    int idx = rg*2 + j;
                    float p = __expf(s[nf][idx] - mn);
                    s[nf][idx] = p;
                    ls += p;
                }
            ls += __shfl_xor_sync(0xffffffffu, ls, 1);
            ls += __shfl_xor_sync(0xffffffffu, ls, 2);
            l[rg] = l[rg]*al + ls;
            m[rg] = mn;
            #pragma unroll
            for (int nf = 0; nf < 8; nf++)
                #pragma unroll
                for (int j = 0; j < 2; j++) o[nf][rg*2 + j] *= al;
        }

        // ---- O += P @ V
        #pragma unroll
        for (int g2 = 0; g2 < 4; g2++) {
            uint32_t ph[4], pl[4];
            #pragma unroll
            for (int half = 0; half < 2; half++) {
                float* sp = s[2*g2 + half];
                float r0 = sp[0] - __bfloat162float(__float2bfloat16(sp[0]));
                float r1 = sp[1] - __bfloat162float(__float2bfloat16(sp[1]));
                float r2 = sp[2] - __bfloat162float(__float2bfloat16(sp[2]));
                float r3 = sp[3] - __bfloat162float(__float2bfloat16(sp[3]));
                ph[2*half]     = pack_bf2(sp[0], sp[1]);
                ph[2*half + 1] = pack_bf2(sp[2], sp[3]);
                pl[2*half]     = pack_bf2(r0, r1);
                pl[2*half + 1] = pack_bf2(r2, r3);
            }
            #pragma unroll
            for (int np = 0; np < 4; np++) {
                uint32_t ro = stb + bro + (uint32_t)np*16*STRB + g2*32;
                uint32_t th[4], tl[4];
                LDSM4(th, ro + 2*ATSZ);
                LDSM4(tl, ro + 3*ATSZ);
                mma16816(o[2*np],     ph, th);
                mma16816(o[2*np],     ph, tl);
                mma16816(o[2*np],     pl, th);
                mma16816(o[2*np + 1], ph, th + 2);
                mma16816(o[2*np + 1], ph, tl + 2);
                mma16816(o[2*np + 1], pl, th + 2);
            }
        }
        __syncthreads();
    }

    // ---- epilogue
    float inv[2] = {1.f / l[0], 1.f / l[1]};
    #pragma unroll
    for (int nf = 0; nf < 8; nf++)
        #pragma unroll
        for (int rg = 0; rg < 2; rg++)
            #pragma unroll
            for (int j = 0; j < 2; j++) {
                int sq = q0 + w*16 + (lane >> 2) + rg*8;
                int d  = nf*8 + (lane & 3)*2 + j;
                float v = o[nf][rg*2 + j] * inv[rg];
                size_t off = ((size_t)b*NS + sq)*ND + h*DH + d;
                __nv_bfloat16 hh = __float2bfloat16(v);
                g_aohi[off] = hh;
                g_aolo[off] = __float2bfloat16(v - __bfloat162float(hh));
            }
}

// ---------------- output projection -> d_out -------------------------------
__global__ __launch_bounds__(256) void k_out_mma(const float* __restrict__ bo,
                                                 float* __restrict__ out) {
    extern __shared__ char dsm[];
    const int brow = blockIdx.y * 128, bcol = blockIdx.x * 128;
    const __nv_bfloat16* wh = g_wthi + (size_t)3*ND*ND + (size_t)bcol*ND;
    const __nv_bfloat16* wl = g_wtlo + (size_t)3*ND*ND + (size_t)bcol*ND;
    float acc[64];
    hmma_core<128, 64, 32>(g_aohi + (size_t)brow*ND, g_aolo + (size_t)brow*ND, ND,
                           wh, wl, ND, ND, dsm, acc);
    const int lane = threadIdx.x & 31, w = threadIdx.x >> 5;
    const int wm = w >> 2, wn = w & 3;
    #pragma unroll
    for (int mt = 0; mt < 4; mt++)
        #pragma unroll
        for (int nt = 0; nt < 4; nt++) {
            int row = brow + wm*64 + mt*16 + (lane >> 2);
            int col = bcol + wn*32 + nt*8 + (lane & 3)*2;
            float* c = acc + (mt*4 + nt)*4;
            float* o0 = out + (size_t)row*ND + col;
            *(float2*)o0 = make_float2(c[0] + bo[col], c[1] + bo[col + 1]);
            *(float2*)(o0 + 8*(size_t)ND) = make_float2(c[2] + bo[col], c[3] + bo[col + 1]);
        }
}

// ---------------------------------------------------------------------------
#define SMEM_N128 (2*4*128*STRB)            // 147456: two pipeline stages

extern "C" void kernel_launch(void* const* d_in, const int* in_sizes, int n_in,
                              void* d_out, int out_size) {
    const float* x    = (const float*)d_in[0];
    const int*   mask = (const int*)  d_in[1];
    const float* wq   = (const float*)d_in[2];
    const float* bq   = (const float*)d_in[3];
    const float* wk   = (const float*)d_in[4];
    const float* bk   = (const float*)d_in[5];
    const float* wv   = (const float*)d_in[6];
    const float* bv   = (const float*)d_in[7];
    const float* wo   = (const float*)d_in[8];
    const float* bo   = (const float*)d_in[9];
    float* out = (float*)d_out;

    cudaFuncSetAttribute(k_qkv_mma, cudaFuncAttributeMaxDynamicSharedMemorySize, SMEM_N128);
    cudaFuncSetAttribute(k_attn,    cudaFuncAttributeMaxDynamicSharedMemorySize, ATT_SMEM);
    cudaFuncSetAttribute(k_out_mma, cudaFuncAttributeMaxDynamicSharedMemorySize, SMEM_N128);

    // 1. input + weight conversions, RoPE table
    k_convert_x<<<NM*ND/256, 256>>>(x);
    k_wtrans<<<dim3(32, 32, 4), dim3(32, 8)>>>(wq, wk, wv, wo);
    k_rope_tab<<<NS*32/256, 256>>>();

    // 2. QKV projections (HMMA, cp.async pipeline) + fused bias/RoPE/split/V^T
    k_qkv_mma<<<dim3(ND/128, NM/128, 3), 256, SMEM_N128>>>(bq, bk, bv);

    // 3. fused flash attention (cp.async 2-stage KV pipeline)
    k_attn<<<dim3(NS/128, BHT), 256, ATT_SMEM>>>(mask);

    // 4. output projection
    k_out_mma<<<dim3(ND/128, NM/128, 1), 256, SMEM_N128>>>(bo, out);
}